// round 14
// baseline (speedup 1.0000x reference)
#include <cuda_runtime.h>
#include <cuda_bf16.h>

#define SEQ   4096
#define BATCH 256
#define DIN   64
#define DH    128

// Scratch for precomputed input projections x_proj[s][b][j].
__device__ float g_xproj[SEQ * BATCH * DH];

// ---------------------------------------------------------------------------
// Packed fp32x2 helpers (Blackwell: 2 FMAs per instruction, rt=2/SMSP).
// ---------------------------------------------------------------------------
__device__ __forceinline__ unsigned long long pack2(float lo, float hi) {
    unsigned long long r;
    asm("mov.b64 %0, {%1, %2};" : "=l"(r) : "f"(lo), "f"(hi));
    return r;
}

__device__ __forceinline__ float2 unpack2(unsigned long long v) {
    float2 f;
    asm("mov.b64 {%0, %1}, %2;" : "=f"(f.x), "=f"(f.y) : "l"(v));
    return f;
}

__device__ __forceinline__ void ffma2(unsigned long long& d,
                                      unsigned long long a,
                                      unsigned long long b) {
    asm("fma.rn.f32x2 %0, %1, %2, %0;" : "+l"(d) : "l"(a), "l"(b));
}

__device__ __forceinline__ unsigned long long fadd2(unsigned long long a,
                                                    unsigned long long b) {
    unsigned long long d;
    asm("add.rn.f32x2 %0, %1, %2;" : "=l"(d) : "l"(a), "l"(b));
    return d;
}

// tanh via 2x MUFU (EX2 + RCP), rel err ~2^-20 (tanh.approx's ~5e-4 would
// accumulate too close to the 1e-3 gate over 4096 steps; this keeps ~3e-7).
__device__ __forceinline__ float fast_tanh(float x) {
    float e = __expf(x + x);
    return 1.0f - __fdividef(2.0f, e + 1.0f);
}

// ---------------------------------------------------------------------------
// Phase 1: x_proj[s,b,j] = dot(input[s,b,:], W_ih[j,:]) + b_ih[j] + b_hh[j]
// Double-buffered smem tiles; one __syncthreads per tile.
// ---------------------------------------------------------------------------
__global__ void __launch_bounds__(128) xproj_kernel(
    const float* __restrict__ in,     // [SEQ*BATCH, DIN]
    const float* __restrict__ Wih,    // [DH, DIN]
    const float* __restrict__ bA,
    const float* __restrict__ bB)
{
    __shared__ __align__(16) float sbuf[2][16 * DIN];   // 2 x 4 KB tiles

    const int j = threadIdx.x;

    unsigned long long wp[32];
#pragma unroll
    for (int q = 0; q < 16; q++) {
        float4 v = *(const float4*)(Wih + j * DIN + q * 4);
        wp[2 * q]     = pack2(v.x, v.y);
        wp[2 * q + 1] = pack2(v.z, v.w);
    }
    const float bias = bA[j] + bB[j];

    const int ntiles = (SEQ * BATCH) / 16;
    int tile = blockIdx.x;

    float4 r0, r1;
    if (tile < ntiles) {
        const float4* src = (const float4*)(in + tile * (16 * DIN));
        r0 = src[j];
        r1 = src[128 + j];
    }

    int p = 0;
    for (; tile < ntiles; tile += gridDim.x) {
        ((float4*)sbuf[p])[j]       = r0;
        ((float4*)sbuf[p])[128 + j] = r1;
        __syncthreads();

        const int next = tile + gridDim.x;
        if (next < ntiles) {
            const float4* src = (const float4*)(in + next * (16 * DIN));
            r0 = src[j];
            r1 = src[128 + j];
        }

        const float* tb = sbuf[p];
        float* dst = &g_xproj[tile * (16 * DH) + j];
#pragma unroll 4
        for (int r = 0; r < 16; r++) {
            unsigned long long acc[4] = {0ULL, 0ULL, 0ULL, 0ULL};
#pragma unroll
            for (int q = 0; q < 16; q++) {
                ulonglong2 hv = *(const ulonglong2*)(tb + r * DIN + q * 4);
                ffma2(acc[(q & 1) * 2],     wp[2 * q],     hv.x);
                ffma2(acc[(q & 1) * 2 + 1], wp[2 * q + 1], hv.y);
            }
            unsigned long long t = fadd2(fadd2(acc[0], acc[1]),
                                         fadd2(acc[2], acc[3]));
            float2 f = unpack2(t);
            __stcs(dst + r * DH, f.x + f.y + bias);
        }
        p ^= 1;
    }
}

// ---------------------------------------------------------------------------
// Phase 2: sequential scan. 256 blocks x 256 threads, one row per block,
// 2 CTAs/SM.
//
// Quarter-k split to SHORTEN THE CRITICAL PATH at fixed pipe floors
// (R13 diagnosis: no pipe binding; step = single-warp serial path through
// the barrier). Thread (g = t>>2, q = t&3) owns units {g, g+64} over
// k in [32q, 32q+32):
//   - 32 FFMA2/thread -> chain issue 64 cyc/warp (was 128)
//   - 8 x LDS.128/thread, ratio 1:4 kept -> same per-SM MIO as R13
//   - h chunks skewed by 16B (36-float stride) -> lane-q bases at
//     0/16/32/48 B mod 128: conflict-free (validated in R7)
//   - 2-level shfl reduction; lanes q=0 / q=1 finalize g / g+64 in
//     parallel (one tanh depth on the path, MUFU spread over 2x lanes)
//   - 8 warps/CTA, 2 CTAs/SM -> 4 warps/SMSP to fill the tail windows
// ---------------------------------------------------------------------------
#define CS 36                          // skewed chunk stride (32 + 4 pad)
#define HBUF_LEN (4 * CS)              // 144

__device__ __forceinline__ int hpos(int k) { return (k >> 5) * CS + (k & 31); }

__global__ void __launch_bounds__(256, 2) rnn_scan_kernel(
    const float* __restrict__ Whh,    // [DH, DH]
    float* __restrict__ out)          // [BATCH, DH]
{
    const int t   = threadIdx.x;
    const int g   = t >> 2;           // unit-pair id: units {g, g+64}
    const int q   = t & 3;            // k-quarter [32q, 32q+32)
    const int row = blockIdx.x;
    const int STRIDE = BATCH * DH;

    __shared__ __align__(16) float h0buf[HBUF_LEN];
    __shared__ __align__(16) float h1buf[HBUF_LEN];

    // W slices: rows g and g+64, k in [32q, 32q+32). 16 u64 each (64 regs).
    unsigned long long wa[16], wb[16];
    {
        const float* ra = Whh + g * DH + q * 32;
        const float* rb = ra + 64 * DH;
#pragma unroll
        for (int c = 0; c < 8; c++) {
            float4 va = *(const float4*)(ra + c * 4);
            float4 vb = *(const float4*)(rb + c * 4);
            wa[2 * c]     = pack2(va.x, va.y);
            wa[2 * c + 1] = pack2(va.z, va.w);
            wb[2 * c]     = pack2(vb.x, vb.y);
            wb[2 * c + 1] = pack2(vb.z, vb.w);
        }
    }

    if (t < HBUF_LEN) h0buf[t] = 0.0f;          // h0 = 0 (incl. pads)

    // Finalizing lanes: q==0 -> unit g, q==1 -> unit g+64.
    const bool fin   = (q < 2);
    const int  xunit = g + 64 * q;              // valid for q<2
    const float* xcol = &g_xproj[row * DH + (fin ? xunit : 0)];

    float xc = fin ? __ldcs(xcol) : 0.0f;
    float xn = fin ? __ldcs(xcol + STRIDE) : 0.0f;
    const float* xp = xcol + 2 * STRIDE;

    __syncthreads();

    float hn = 0.0f;
#pragma unroll 1
    for (int s = 0; s < SEQ; s += 2) {
#pragma unroll
        for (int half = 0; half < 2; half++) {
            const float* hb = half ? h1buf : h0buf;
            float*       nb = half ? h0buf : h1buf;

            float xf = (fin && s + 2 + half < SEQ)
                           ? __ldcs(xp + half * STRIDE) : 0.0f;

            const ulonglong2* hv = (const ulonglong2*)(hb + q * CS);
            unsigned long long aA0 = 0ULL, aA1 = 0ULL;
            unsigned long long aB0 = 0ULL, aB1 = 0ULL;
#pragma unroll
            for (int c = 0; c < 8; c++) {        // 8 x LDS.128
                ulonglong2 p = hv[c];
                ffma2(aA0, wa[2 * c],     p.x);
                ffma2(aA1, wa[2 * c + 1], p.y);
                ffma2(aB0, wb[2 * c],     p.x);
                ffma2(aB1, wb[2 * c + 1], p.y);
            }
            float2 fA = unpack2(fadd2(aA0, aA1));
            float2 fB = unpack2(fadd2(aB0, aB1));
            float pa = fA.x + fA.y;              // partial of unit g
            float pb = fB.x + fB.y;              // partial of unit g+64

            // Combine the 4 k-quarters (lanes 4g..4g+3).
            pa += __shfl_xor_sync(0xFFFFFFFFu, pa, 1);
            pb += __shfl_xor_sync(0xFFFFFFFFu, pb, 1);
            pa += __shfl_xor_sync(0xFFFFFFFFu, pa, 2);
            pb += __shfl_xor_sync(0xFFFFFFFFu, pb, 2);

            if (fin) {
                hn = fast_tanh(xc + (q == 0 ? pa : pb));
                nb[hpos(xunit)] = hn;
            }
            xc = xn; xn = xf;
            __syncthreads();
        }
        xp += 2 * STRIDE;
    }

    if (fin) out[row * DH + xunit] = hn;
}

// ---------------------------------------------------------------------------
// Launch.
// ---------------------------------------------------------------------------
extern "C" void kernel_launch(void* const* d_in, const int* in_sizes, int n_in,
                              void* d_out, int out_size) {
    const float* input = nullptr;
    const float* Wih   = nullptr;
    const float* Whh   = nullptr;
    const float* bA    = nullptr;
    const float* bB    = nullptr;

    for (int i = 0; i < n_in; i++) {
        const int sz = in_sizes[i];
        const float* p = (const float*)d_in[i];
        if      (sz == SEQ * BATCH * DIN) input = p;
        else if (sz == DH * DIN)          Wih   = p;
        else if (sz == DH * DH)           Whh   = p;
        else if (sz == DH)                { if (!bA) bA = p; else bB = p; }
    }

    xproj_kernel<<<2048, 128>>>(input, Wih, bA, bB);
    rnn_scan_kernel<<<BATCH, 256>>>(Whh, (float*)d_out);
}

// round 15
// speedup vs baseline: 1.2174x; 1.2174x over previous
#include <cuda_runtime.h>
#include <cuda_bf16.h>

#define SEQ   4096
#define BATCH 256
#define DIN   64
#define DH    128

// Scratch for precomputed input projections x_proj[s][b][j].
__device__ float g_xproj[SEQ * BATCH * DH];

// ---------------------------------------------------------------------------
// Packed fp32x2 helpers (Blackwell: 2 FMAs per instruction, rt=2/SMSP).
// ---------------------------------------------------------------------------
__device__ __forceinline__ unsigned long long pack2(float lo, float hi) {
    unsigned long long r;
    asm("mov.b64 %0, {%1, %2};" : "=l"(r) : "f"(lo), "f"(hi));
    return r;
}

__device__ __forceinline__ float2 unpack2(unsigned long long v) {
    float2 f;
    asm("mov.b64 {%0, %1}, %2;" : "=f"(f.x), "=f"(f.y) : "l"(v));
    return f;
}

__device__ __forceinline__ void ffma2(unsigned long long& d,
                                      unsigned long long a,
                                      unsigned long long b) {
    asm("fma.rn.f32x2 %0, %1, %2, %0;" : "+l"(d) : "l"(a), "l"(b));
}

__device__ __forceinline__ unsigned long long fadd2(unsigned long long a,
                                                    unsigned long long b) {
    unsigned long long d;
    asm("add.rn.f32x2 %0, %1, %2;" : "=l"(d) : "l"(a), "l"(b));
    return d;
}

// tanh via 2x MUFU (EX2 + RCP), rel err ~2^-20. (tanh.approx.f32's ~5e-4
// per-step error amplified ~4x over the scan would breach the 1e-3 gate.)
__device__ __forceinline__ float fast_tanh(float x) {
    float e = __expf(x + x);
    return 1.0f - __fdividef(2.0f, e + 1.0f);
}

// ---------------------------------------------------------------------------
// Phase 1: x_proj[s,b,j] = dot(input[s,b,:], W_ih[j,:]) + b_ih[j] + b_hh[j]
//
// MIO-balanced layout: thread (u = t&63, rg = t>>6) owns TWO units
// {u, u+64} at full k=64 (W = 128 regs) and processes row-group rg's 8 rows
// of the 16-row tile. Each LDS.128 of x now feeds 4 FFMA2 (ratio 1:4, was
// 1:1) — phase 1 was MIO-bound, this halves its binding pipe.
// Double-buffered smem tiles; one __syncthreads per tile.
// ---------------------------------------------------------------------------
__global__ void __launch_bounds__(128) xproj_kernel(
    const float* __restrict__ in,     // [SEQ*BATCH, DIN]
    const float* __restrict__ Wih,    // [DH, DIN]
    const float* __restrict__ bA,
    const float* __restrict__ bB)
{
    __shared__ __align__(16) float sbuf[2][16 * DIN];   // 2 x 4 KB tiles

    const int t  = threadIdx.x;
    const int u  = t & 63;            // unit pair {u, u+64}
    const int rg = t >> 6;            // row group: rows [8rg, 8rg+8)

    // W_ih rows u and u+64 (64 floats each -> 32 packed u64 each).
    unsigned long long wa[32], wb[32];
    {
        const float* rwa = Wih + u * DIN;
        const float* rwb = Wih + (u + 64) * DIN;
#pragma unroll
        for (int q = 0; q < 16; q++) {
            float4 va = *(const float4*)(rwa + q * 4);
            float4 vb = *(const float4*)(rwb + q * 4);
            wa[2 * q]     = pack2(va.x, va.y);
            wa[2 * q + 1] = pack2(va.z, va.w);
            wb[2 * q]     = pack2(vb.x, vb.y);
            wb[2 * q + 1] = pack2(vb.z, vb.w);
        }
    }
    const float biasA = bA[u]      + bB[u];
    const float biasB = bA[u + 64] + bB[u + 64];

    const int ntiles = (SEQ * BATCH) / 16;
    int tile = blockIdx.x;

    float4 r0, r1;
    if (tile < ntiles) {
        const float4* src = (const float4*)(in + tile * (16 * DIN));
        r0 = src[t];
        r1 = src[128 + t];
    }

    int p = 0;
    for (; tile < ntiles; tile += gridDim.x) {
        ((float4*)sbuf[p])[t]       = r0;
        ((float4*)sbuf[p])[128 + t] = r1;
        __syncthreads();

        const int next = tile + gridDim.x;
        if (next < ntiles) {
            const float4* src = (const float4*)(in + next * (16 * DIN));
            r0 = src[t];
            r1 = src[128 + t];
        }

        const float* tb = sbuf[p] + (rg * 8) * DIN;
        float* dst = &g_xproj[(tile * 16 + rg * 8) * DH];
#pragma unroll 2
        for (int r = 0; r < 8; r++) {
            const ulonglong2* xv = (const ulonglong2*)(tb + r * DIN);
            unsigned long long aA0 = 0ULL, aA1 = 0ULL;
            unsigned long long aB0 = 0ULL, aB1 = 0ULL;
#pragma unroll
            for (int q = 0; q < 16; q++) {        // 16 LDS.128 -> 64 FFMA2
                ulonglong2 hv = xv[q];
                ffma2(aA0, wa[2 * q],     hv.x);
                ffma2(aA1, wa[2 * q + 1], hv.y);
                ffma2(aB0, wb[2 * q],     hv.x);
                ffma2(aB1, wb[2 * q + 1], hv.y);
            }
            float2 fA = unpack2(fadd2(aA0, aA1));
            float2 fB = unpack2(fadd2(aB0, aB1));
            __stcs(dst + r * DH + u,      fA.x + fA.y + biasA);
            __stcs(dst + r * DH + u + 64, fB.x + fB.y + biasB);
        }
        p ^= 1;
    }
}

// ---------------------------------------------------------------------------
// Phase 2: sequential scan. 128 blocks x 256 threads, TWO rows per block,
// ONE CTA per SM (grid 128 <= 148 SMs).
//
// Each row uses the R13 lane-pair layout (best so far: 16 LDS.128 + 1 shfl
// + 64 FFMA2 per thread, conflict-free padded h):
//   thread tr in a row: lane pair (2i, 2i+1) jointly owns units {2i, 2i+1};
//   even lane covers k in [0,64), odd lane k in [64,128); one shfl.xor(1)
//   completes both units.
// The two rows are INDEPENDENT pipelines with per-row named barriers
// (bar.sync 1/2, 128) AND an explicit ~200-cycle phase-offset primer on
// row B (serial FMA chain, numerically exact no-op), so row A's serial
// tail (LDS-wait/reduce/shfl/tanh/BAR) overlaps row B's FFMA issue burst
// on each SMSP and vice versa — breaking the lockstep that R5-R13's
// phase-locked identical pipelines never escaped.
// ---------------------------------------------------------------------------
#define HPAD 68                       // padded offset of h[64..127]
#define HBUF_LEN 132                  // 64 + 4 pad + 64

__device__ __forceinline__ int hpos(int k) { return (k < 64) ? k : (k + 4); }

__global__ void __launch_bounds__(256, 1) rnn_scan_kernel(
    const float* __restrict__ Whh,    // [DH, DH]
    float* __restrict__ out)          // [BATCH, DH]
{
    const int t    = threadIdx.x;
    const int rsel = t >> 7;          // 0 = row A (warps 0-3), 1 = row B (4-7)
    const int tr   = t & 127;         // thread-in-row; finalizes unit tr
    const int odd  = tr & 1;
    const int ja   = tr & ~1;
    const int row  = blockIdx.x * 2 + rsel;
    const int STRIDE = BATCH * DH;

    __shared__ __align__(16) float hb[2][2][HBUF_LEN];   // [rsel][phase][..]

    // W slices: rows ja and ja+1, k in [64*odd, 64*odd+64). 32 u64 each.
    unsigned long long wa[32], wb[32];
    {
        const float* ra = Whh + ja * DH + odd * 64;
        const float* rb = ra + DH;
#pragma unroll
        for (int q = 0; q < 16; q++) {
            float4 va = *(const float4*)(ra + q * 4);
            float4 vb = *(const float4*)(rb + q * 4);
            wa[2 * q]     = pack2(va.x, va.y);
            wa[2 * q + 1] = pack2(va.z, va.w);
            wb[2 * q]     = pack2(vb.x, vb.y);
            wb[2 * q + 1] = pack2(vb.z, vb.w);
        }
    }

    hb[rsel][0][hpos(tr)] = 0.0f;     // h0 = 0

    const float* xcol = &g_xproj[row * DH + tr];
    float xc = __ldcs(xcol);
    float xn = __ldcs(xcol + STRIDE);
    const float* xp = xcol + 2 * STRIDE;

    __syncthreads();                  // covers init of both rows' buffers

    // Phase-offset primer: row B burns ~200 cycles in a serial FMA chain.
    // d stays bounded (|d| <= ~1.4), so xc += 0.0f*d is numerically exact.
    if (rsel) {
        float d = Whh[tr];
#pragma unroll
        for (int i = 0; i < 48; i++) d = fmaf(d, 0.25f, 1.0f);
        xc += 0.0f * d;
    }

    const int barid = 1 + rsel;       // named barrier per row
    const int hoff  = odd * HPAD;     // this lane's 64-float h-slice
    float hn = 0.0f;

#pragma unroll 1
    for (int s = 0; s < SEQ; s += 2) {
#pragma unroll
        for (int half = 0; half < 2; half++) {
            const float* hbp = hb[rsel][half];       // read buffer
            float*       nbp = hb[rsel][half ^ 1];   // write buffer

            float xf = (s + 2 + half < SEQ) ? __ldcs(xp + half * STRIDE) : 0.0f;

            const ulonglong2* hv = (const ulonglong2*)(hbp + hoff);
            unsigned long long aA[4] = {0ULL, 0ULL, 0ULL, 0ULL};
            unsigned long long aB[4] = {0ULL, 0ULL, 0ULL, 0ULL};
#pragma unroll
            for (int q = 0; q < 16; q++) {           // 16 x LDS.128
                ulonglong2 p = hv[q];
                ffma2(aA[(2 * q)     & 3], wa[2 * q],     p.x);
                ffma2(aA[(2 * q + 1) & 3], wa[2 * q + 1], p.y);
                ffma2(aB[(2 * q)     & 3], wb[2 * q],     p.x);
                ffma2(aB[(2 * q + 1) & 3], wb[2 * q + 1], p.y);
            }
            unsigned long long uA = fadd2(fadd2(aA[0], aA[1]),
                                          fadd2(aA[2], aA[3]));
            unsigned long long uB = fadd2(fadd2(aB[0], aB[1]),
                                          fadd2(aB[2], aB[3]));
            float2 fA = unpack2(uA), fB = unpack2(uB);
            float pa = fA.x + fA.y;                  // partial of unit ja
            float pb = fB.x + fB.y;                  // partial of unit ja+1

            // One exchange completes both units of the lane pair.
            float send = odd ? pa : pb;
            float recv = __shfl_xor_sync(0xFFFFFFFFu, send, 1);
            float sum  = (odd ? pb : pa) + recv;     // full dot for unit tr

            hn = fast_tanh(xc + sum);
            nbp[hpos(tr)] = hn;

            xc = xn; xn = xf;
            asm volatile("bar.sync %0, 128;" :: "r"(barid) : "memory");
        }
        xp += 2 * STRIDE;
    }

    out[row * DH + tr] = hn;
}

// ---------------------------------------------------------------------------
// Launch.
// ---------------------------------------------------------------------------
extern "C" void kernel_launch(void* const* d_in, const int* in_sizes, int n_in,
                              void* d_out, int out_size) {
    const float* input = nullptr;
    const float* Wih   = nullptr;
    const float* Whh   = nullptr;
    const float* bA    = nullptr;
    const float* bB    = nullptr;

    for (int i = 0; i < n_in; i++) {
        const int sz = in_sizes[i];
        const float* p = (const float*)d_in[i];
        if      (sz == SEQ * BATCH * DIN) input = p;
        else if (sz == DH * DIN)          Wih   = p;
        else if (sz == DH * DH)           Whh   = p;
        else if (sz == DH)                { if (!bA) bA = p; else bB = p; }
    }

    xproj_kernel<<<2048, 128>>>(input, Wih, bA, bB);
    rnn_scan_kernel<<<BATCH / 2, 256>>>(Whh, (float*)d_out);
}

// round 16
// speedup vs baseline: 1.2532x; 1.0294x over previous
#include <cuda_runtime.h>
#include <cuda_bf16.h>

#define SEQ   4096
#define BATCH 256
#define DIN   64
#define DH    128

// ---------------------------------------------------------------------------
// Packed fp32x2 helpers (Blackwell: 2 FMAs per instruction, rt=2/SMSP).
// ---------------------------------------------------------------------------
__device__ __forceinline__ unsigned long long pack2(float lo, float hi) {
    unsigned long long r;
    asm("mov.b64 %0, {%1, %2};" : "=l"(r) : "f"(lo), "f"(hi));
    return r;
}

__device__ __forceinline__ float2 unpack2(unsigned long long v) {
    float2 f;
    asm("mov.b64 {%0, %1}, %2;" : "=f"(f.x), "=f"(f.y) : "l"(v));
    return f;
}

__device__ __forceinline__ void ffma2(unsigned long long& d,
                                      unsigned long long a,
                                      unsigned long long b) {
    asm("fma.rn.f32x2 %0, %1, %2, %0;" : "+l"(d) : "l"(a), "l"(b));
}

__device__ __forceinline__ unsigned long long fadd2(unsigned long long a,
                                                    unsigned long long b) {
    unsigned long long d;
    asm("add.rn.f32x2 %0, %1, %2;" : "=l"(d) : "l"(a), "l"(b));
    return d;
}

// tanh via 2x MUFU (EX2 + RCP), rel err ~2^-20.
__device__ __forceinline__ float fast_tanh(float x) {
    float e = __expf(x + x);
    return 1.0f - __fdividef(2.0f, e + 1.0f);
}

// ---------------------------------------------------------------------------
// Fully fused RNN: ONE kernel, 256 blocks x 128 threads (one batch row per
// block, 2 CTAs/SM — the R13 chassis, best measured scan).
//
// Scan layout (unchanged from R13): lane pair (2i, 2i+1) jointly owns units
// {2i, 2i+1}; even lane covers k in [0,64), odd k in [64,128); 16 LDS.128 +
// 64 FFMA2 + one shfl.xor(1) per thread per step; h stored with 16B skew
// (HPAD) so even/odd lanes hit disjoint banks.
//
// NEW — fused input projection: the scan runs at 29% issue (71% idle slots,
// no binding pipe). x_{s+1} = W_ih . input[s+1] + b is INDEPENDENT of the
// recurrence, so it is computed inside step s as stall-filler:
//   - same lane-pair split: thread holds W_ih rows {ja, ja+1} over its
//     32-element k-slice (64 regs); 8 LDS.128 + 32 FFMA2 + 1 shfl
//   - input rows stream DRAM -> regs -> smem 4-slot ring; the LDG for
//     input[s+4] is issued one full step (~700 cyc > 577 DRAM) before its
//     STS, and read two steps later
// This deletes the standalone xproj kernel, the 512 MB scratch, and all of
// its DRAM traffic: total time = scan time alone.
// ---------------------------------------------------------------------------
#define HPAD 68                       // padded offset of h[64..127]
#define HBUF_LEN 132                  // 64 + 4 pad + 64
#define INS  72                       // input slot stride: 32 | 4 pad | 32 +4

__device__ __forceinline__ int hpos(int k) { return (k < 64) ? k : (k + 4); }
// input slot float-offset for element k (0..63): lo half at 0, hi at 36.
__device__ __forceinline__ int ipos(int k) { return (k < 32) ? k : (k + 4); }

__global__ void __launch_bounds__(128, 2) rnn_fused_kernel(
    const float* __restrict__ in,     // [SEQ, BATCH, DIN]
    const float* __restrict__ Wih,    // [DH, DIN]
    const float* __restrict__ Whh,    // [DH, DH]
    const float* __restrict__ bA,     // [DH]
    const float* __restrict__ bB,     // [DH]
    float* __restrict__ out)          // [BATCH, DH]
{
    const int t   = threadIdx.x;      // finalizes unit t
    const int odd = t & 1;
    const int ja  = t & ~1;
    const int row = blockIdx.x;

    __shared__ __align__(16) float hb[2][HBUF_LEN];
    __shared__ __align__(16) float inbuf[4][INS];

    // --- W_hh slices: rows ja, ja+1, k in [64*odd, 64*odd+64). 128 regs. ---
    unsigned long long wa[32], wb[32];
    {
        const float* ra = Whh + ja * DH + odd * 64;
        const float* rb = ra + DH;
#pragma unroll
        for (int q = 0; q < 16; q++) {
            float4 va = *(const float4*)(ra + q * 4);
            float4 vb = *(const float4*)(rb + q * 4);
            wa[2 * q]     = pack2(va.x, va.y);
            wa[2 * q + 1] = pack2(va.z, va.w);
            wb[2 * q]     = pack2(vb.x, vb.y);
            wb[2 * q + 1] = pack2(vb.z, vb.w);
        }
    }

    // --- W_ih slices: rows ja, ja+1, k in [32*odd, 32*odd+32). 64 regs. ---
    unsigned long long wiA[16], wiB[16];
    {
        const float* ia = Wih + ja * DIN + odd * 32;
        const float* ib = ia + DIN;
#pragma unroll
        for (int c = 0; c < 8; c++) {
            float4 va = *(const float4*)(ia + c * 4);
            float4 vb = *(const float4*)(ib + c * 4);
            wiA[2 * c]     = pack2(va.x, va.y);
            wiA[2 * c + 1] = pack2(va.z, va.w);
            wiB[2 * c]     = pack2(vb.x, vb.y);
            wiB[2 * c + 1] = pack2(vb.z, vb.w);
        }
    }
    const float biasX = bA[t] + bB[t];   // x gets b_ih + b_hh (ref semantics)

    // --- Prologue: stage input[0..3] into the 4-slot ring; h0 = 0. ---
    if (t < 64) {
        const int slot = t >> 4, idx = t & 15;
        float4 v = ((const float4*)(in + ((size_t)slot * BATCH + row) * DIN))[idx];
        *(float4*)&inbuf[slot][ipos(idx * 4)] = v;
    }
    hb[0][hpos(t)] = 0.0f;
    __syncthreads();

    // Fused x-projection for one staged input slot (lane-pair split).
    auto xproj_eval = [&](const float* slot) -> float {
        const ulonglong2* xv = (const ulonglong2*)(slot + odd * 36);
        unsigned long long a0 = 0ULL, a1 = 0ULL, b0 = 0ULL, b1 = 0ULL;
#pragma unroll
        for (int c = 0; c < 8; c++) {             // 8 x LDS.128
            ulonglong2 p = xv[c];
            ffma2(a0, wiA[2 * c],     p.x);
            ffma2(a1, wiA[2 * c + 1], p.y);
            ffma2(b0, wiB[2 * c],     p.x);
            ffma2(b1, wiB[2 * c + 1], p.y);
        }
        float2 fa = unpack2(fadd2(a0, a1));
        float2 fb = unpack2(fadd2(b0, b1));
        float pa = fa.x + fa.y;                   // partial of unit ja
        float pb = fb.x + fb.y;                   // partial of unit ja+1
        float send = odd ? pa : pb;
        float recv = __shfl_xor_sync(0xFFFFFFFFu, send, 1);
        return ((odd ? pb : pa) + recv) + biasX;  // full x for unit t
    };

    float xc = xproj_eval(inbuf[0]);              // x_0

    // held = input[4] (written to the ring during step 0).
    float4 held = make_float4(0.f, 0.f, 0.f, 0.f);
    if (t < 16)
        held = ((const float4*)(in + ((size_t)4 * BATCH + row) * DIN))[t];

    const int hoff = odd * HPAD;
    float hn = 0.0f;

#pragma unroll 1
    for (int s = 0; s < SEQ; s += 2) {
#pragma unroll
        for (int half = 0; half < 2; half++) {
            const int ss = s + half;

            // --- fused xproj for step ss+1 (stall-filler; at ss=4095 the
            //     result is garbage-but-finite and unused) ---
            float xn = xproj_eval(inbuf[(ss + 1) & 3]);

            // --- recurrence step ss: consume xc ---
            const float* hbp = hb[half];
            const ulonglong2* hv = (const ulonglong2*)(hbp + hoff);
            unsigned long long aA[4] = {0ULL, 0ULL, 0ULL, 0ULL};
            unsigned long long aB[4] = {0ULL, 0ULL, 0ULL, 0ULL};
#pragma unroll
            for (int q = 0; q < 16; q++) {        // 16 x LDS.128
                ulonglong2 p = hv[q];
                ffma2(aA[(2 * q)     & 3], wa[2 * q],     p.x);
                ffma2(aA[(2 * q + 1) & 3], wa[2 * q + 1], p.y);
                ffma2(aB[(2 * q)     & 3], wb[2 * q],     p.x);
                ffma2(aB[(2 * q + 1) & 3], wb[2 * q + 1], p.y);
            }
            unsigned long long uA = fadd2(fadd2(aA[0], aA[1]),
                                          fadd2(aA[2], aA[3]));
            unsigned long long uB = fadd2(fadd2(aB[0], aB[1]),
                                          fadd2(aB[2], aB[3]));
            float2 fA = unpack2(uA), fB = unpack2(uB);
            float pa = fA.x + fA.y;
            float pb = fB.x + fB.y;
            float send = odd ? pa : pb;
            float recv = __shfl_xor_sync(0xFFFFFFFFu, send, 1);
            float sum  = (odd ? pb : pa) + recv;

            hn = fast_tanh(xc + sum);
            hb[half ^ 1][hpos(t)] = hn;

            // --- input ring staging: STS input[ss+4] (held since last
            //     step), then LDG input[ss+5] into held ---
            if (t < 16) {
                *(float4*)&inbuf[ss & 3][ipos(t * 4)] = held;   // slot (ss+4)&3
                const int nl = min(ss + 5, SEQ - 1);
                held = ((const float4*)(in + ((size_t)nl * BATCH + row) * DIN))[t];
            }

            xc = xn;
            __syncthreads();
        }
    }

    out[row * DH + t] = hn;
}

// ---------------------------------------------------------------------------
// Launch: single fused kernel.
// ---------------------------------------------------------------------------
extern "C" void kernel_launch(void* const* d_in, const int* in_sizes, int n_in,
                              void* d_out, int out_size) {
    const float* input = nullptr;
    const float* Wih   = nullptr;
    const float* Whh   = nullptr;
    const float* bA    = nullptr;
    const float* bB    = nullptr;

    for (int i = 0; i < n_in; i++) {
        const int sz = in_sizes[i];
        const float* p = (const float*)d_in[i];
        if      (sz == SEQ * BATCH * DIN) input = p;
        else if (sz == DH * DIN)          Wih   = p;
        else if (sz == DH * DH)           Whh   = p;
        else if (sz == DH)                { if (!bA) bA = p; else bB = p; }
    }

    rnn_fused_kernel<<<BATCH, 128>>>(input, Wih, Whh, bA, bB, (float*)d_out);
}

// round 17
// speedup vs baseline: 1.2541x; 1.0007x over previous
#include <cuda_runtime.h>
#include <cuda_bf16.h>

#define SEQ   4096
#define BATCH 256
#define DIN   64
#define DH    128

// ---------------------------------------------------------------------------
// Packed fp32x2 helpers (Blackwell: 2 FMAs per instruction, rt=2/SMSP).
// ---------------------------------------------------------------------------
__device__ __forceinline__ unsigned long long pack2(float lo, float hi) {
    unsigned long long r;
    asm("mov.b64 %0, {%1, %2};" : "=l"(r) : "f"(lo), "f"(hi));
    return r;
}

__device__ __forceinline__ float2 unpack2(unsigned long long v) {
    float2 f;
    asm("mov.b64 {%0, %1}, %2;" : "=f"(f.x), "=f"(f.y) : "l"(v));
    return f;
}

__device__ __forceinline__ void ffma2(unsigned long long& d,
                                      unsigned long long a,
                                      unsigned long long b) {
    asm("fma.rn.f32x2 %0, %1, %2, %0;" : "+l"(d) : "l"(a), "l"(b));
}

__device__ __forceinline__ unsigned long long fadd2(unsigned long long a,
                                                    unsigned long long b) {
    unsigned long long d;
    asm("add.rn.f32x2 %0, %1, %2;" : "=l"(d) : "l"(a), "l"(b));
    return d;
}

// tanh via 2x MUFU (EX2 + RCP), rel err ~2^-20.
__device__ __forceinline__ float fast_tanh(float x) {
    float e = __expf(x + x);
    return 1.0f - __fdividef(2.0f, e + 1.0f);
}

// ---------------------------------------------------------------------------
// Fully fused RNN: ONE kernel, 256 blocks x 128 threads, one row per block,
// 2 CTAs/SM (R16 chassis — best measured).
//
// R17 deltas (critical-path shaving only):
//   1. The x-projection for step s+1 computes only PARTIALS before the
//      recurrence; its shfl-combine + bias is DEFERRED into the tanh/STS
//      shadow after hn is stored (removes a warp-reconvergence point +
//      26-cyc shfl from the pre-tanh path).
//   2. Input-ring staging is spread across all 4 warps (4 lanes each)
//      instead of concentrated in warp 0 (BAR release = max over warps;
//      warp 0 was always last).
// ---------------------------------------------------------------------------
#define HPAD 68                       // padded offset of h[64..127]
#define HBUF_LEN 132                  // 64 + 4 pad + 64
#define INS  72                       // input slot stride: 32 | 4 pad | 32 +4

__device__ __forceinline__ int hpos(int k) { return (k < 64) ? k : (k + 4); }
// input slot float-offset for element k (0..63): lo half at 0, hi at 36.
__device__ __forceinline__ int ipos(int k) { return (k < 32) ? k : (k + 4); }

__global__ void __launch_bounds__(128, 2) rnn_fused_kernel(
    const float* __restrict__ in,     // [SEQ, BATCH, DIN]
    const float* __restrict__ Wih,    // [DH, DIN]
    const float* __restrict__ Whh,    // [DH, DH]
    const float* __restrict__ bA,     // [DH]
    const float* __restrict__ bB,     // [DH]
    float* __restrict__ out)          // [BATCH, DH]
{
    const int t   = threadIdx.x;      // finalizes unit t
    const int odd = t & 1;
    const int ja  = t & ~1;
    const int row = blockIdx.x;

    __shared__ __align__(16) float hb[2][HBUF_LEN];
    __shared__ __align__(16) float inbuf[4][INS];

    // --- W_hh slices: rows ja, ja+1, k in [64*odd, 64*odd+64). 128 regs. ---
    unsigned long long wa[32], wb[32];
    {
        const float* ra = Whh + ja * DH + odd * 64;
        const float* rb = ra + DH;
#pragma unroll
        for (int q = 0; q < 16; q++) {
            float4 va = *(const float4*)(ra + q * 4);
            float4 vb = *(const float4*)(rb + q * 4);
            wa[2 * q]     = pack2(va.x, va.y);
            wa[2 * q + 1] = pack2(va.z, va.w);
            wb[2 * q]     = pack2(vb.x, vb.y);
            wb[2 * q + 1] = pack2(vb.z, vb.w);
        }
    }

    // --- W_ih slices: rows ja, ja+1, k in [32*odd, 32*odd+32). 32 regs. ---
    unsigned long long wiA[16], wiB[16];
    {
        const float* ia = Wih + ja * DIN + odd * 32;
        const float* ib = ia + DIN;
#pragma unroll
        for (int c = 0; c < 8; c++) {
            float4 va = *(const float4*)(ia + c * 4);
            float4 vb = *(const float4*)(ib + c * 4);
            wiA[2 * c]     = pack2(va.x, va.y);
            wiA[2 * c + 1] = pack2(va.z, va.w);
            wiB[2 * c]     = pack2(vb.x, vb.y);
            wiB[2 * c + 1] = pack2(vb.z, vb.w);
        }
    }
    const float biasX = bA[t] + bB[t];   // x gets b_ih + b_hh

    // --- Staging assignment: 4 lanes per warp, warp w stages float4 idx
    //     w*4 + lane (16 float4 = one 64-float input row). ---
    const int lane  = t & 31;
    const bool stg  = (lane < 4);
    const int  sidx = (t >> 5) * 4 + lane;      // 0..15 (valid when stg)

    // --- Prologue: stage input[0..3] into the ring; h0 = 0. ---
    if (t < 64) {
        const int slot = t >> 4, idx = t & 15;
        float4 v = ((const float4*)(in + ((size_t)slot * BATCH + row) * DIN))[idx];
        *(float4*)&inbuf[slot][ipos(idx * 4)] = v;
    }
    hb[0][hpos(t)] = 0.0f;
    __syncthreads();

    // x-projection partials for one staged slot (no shfl — deferred).
    auto xproj_partial = [&](const float* slot, float& pa, float& pb) {
        const ulonglong2* xv = (const ulonglong2*)(slot + odd * 36);
        unsigned long long a0 = 0ULL, a1 = 0ULL, b0 = 0ULL, b1 = 0ULL;
#pragma unroll
        for (int c = 0; c < 8; c++) {             // 8 x LDS.128
            ulonglong2 p = xv[c];
            ffma2(a0, wiA[2 * c],     p.x);
            ffma2(a1, wiA[2 * c + 1], p.y);
            ffma2(b0, wiB[2 * c],     p.x);
            ffma2(b1, wiB[2 * c + 1], p.y);
        }
        float2 fa = unpack2(fadd2(a0, a1));
        float2 fb = unpack2(fadd2(b0, b1));
        pa = fa.x + fa.y;                         // partial of unit ja
        pb = fb.x + fb.y;                         // partial of unit ja+1
    };

    // x_0: full eval (prologue only — shfl inline).
    float xc;
    {
        float pa, pb;
        xproj_partial(inbuf[0], pa, pb);
        float send = odd ? pa : pb;
        float recv = __shfl_xor_sync(0xFFFFFFFFu, send, 1);
        xc = ((odd ? pb : pa) + recv) + biasX;
    }

    // held = input[4] (written to the ring during step 0).
    float4 held = make_float4(0.f, 0.f, 0.f, 0.f);
    if (stg)
        held = ((const float4*)(in + ((size_t)4 * BATCH + row) * DIN))[sidx];

    const int hoff = odd * HPAD;
    float hn = 0.0f;

#pragma unroll 1
    for (int s = 0; s < SEQ; s += 2) {
#pragma unroll
        for (int half = 0; half < 2; half++) {
            const int ss = s + half;

            // --- x partials for step ss+1 (loads issued early; combine
            //     deferred; at ss=4095 result is finite and unused) ---
            float xpa, xpb;
            xproj_partial(inbuf[(ss + 1) & 3], xpa, xpb);

            // --- recurrence step ss: consume xc ---
            const ulonglong2* hv = (const ulonglong2*)(hb[half] + hoff);
            unsigned long long aA[4] = {0ULL, 0ULL, 0ULL, 0ULL};
            unsigned long long aB[4] = {0ULL, 0ULL, 0ULL, 0ULL};
#pragma unroll
            for (int q = 0; q < 16; q++) {        // 16 x LDS.128
                ulonglong2 p = hv[q];
                ffma2(aA[(2 * q)     & 3], wa[2 * q],     p.x);
                ffma2(aA[(2 * q + 1) & 3], wa[2 * q + 1], p.y);
                ffma2(aB[(2 * q)     & 3], wb[2 * q],     p.x);
                ffma2(aB[(2 * q + 1) & 3], wb[2 * q + 1], p.y);
            }
            unsigned long long uA = fadd2(fadd2(aA[0], aA[1]),
                                          fadd2(aA[2], aA[3]));
            unsigned long long uB = fadd2(fadd2(aB[0], aB[1]),
                                          fadd2(aB[2], aB[3]));
            float2 fA = unpack2(uA), fB = unpack2(uB);
            float pa = fA.x + fA.y;
            float pb = fB.x + fB.y;
            float send = odd ? pa : pb;
            float recv = __shfl_xor_sync(0xFFFFFFFFu, send, 1);
            float sum  = (odd ? pb : pa) + recv;

            hn = fast_tanh(xc + sum);
            hb[half ^ 1][hpos(t)] = hn;

            // --- deferred x combine (tanh/STS shadow) ---
            {
                float xs = odd ? xpa : xpb;
                float xr = __shfl_xor_sync(0xFFFFFFFFu, xs, 1);
                xc = ((odd ? xpb : xpa) + xr) + biasX;
            }

            // --- input ring staging (spread across warps): STS
            //     input[ss+4] (held), then LDG input[ss+5] ---
            if (stg) {
                *(float4*)&inbuf[ss & 3][ipos(sidx * 4)] = held;
                const int nl = min(ss + 5, SEQ - 1);
                held = ((const float4*)(in + ((size_t)nl * BATCH + row) * DIN))[sidx];
            }

            __syncthreads();
        }
    }

    out[row * DH + t] = hn;
}

// ---------------------------------------------------------------------------
// Launch: single fused kernel.
// ---------------------------------------------------------------------------
extern "C" void kernel_launch(void* const* d_in, const int* in_sizes, int n_in,
                              void* d_out, int out_size) {
    const float* input = nullptr;
    const float* Wih   = nullptr;
    const float* Whh   = nullptr;
    const float* bA    = nullptr;
    const float* bB    = nullptr;

    for (int i = 0; i < n_in; i++) {
        const int sz = in_sizes[i];
        const float* p = (const float*)d_in[i];
        if      (sz == SEQ * BATCH * DIN) input = p;
        else if (sz == DH * DIN)          Wih   = p;
        else if (sz == DH * DH)           Whh   = p;
        else if (sz == DH)                { if (!bA) bA = p; else bB = p; }
    }

    rnn_fused_kernel<<<BATCH, 128>>>(input, Wih, Whh, bA, bB, (float*)d_out);
}